// round 14
// baseline (speedup 1.0000x reference)
#include <cuda_runtime.h>
#include <math.h>
#include <stdint.h>

#define T_STEPS 64
#define B_SZ    512
#define OBS_    1536
#define ACT_    32
#define D_      2048
#define H_      2048
#define K_      32
#define V_      32
#define S_      1024
#define SL      (B_SZ * D_)
#define TB      (T_STEPS * B_SZ)

// ---------------- device scratch ----------------
__device__ float g_obs_e[(size_t)TB * H_];
__device__ float g_act_e[(size_t)TB * H_];   // also priors hidden scratch
__device__ float g_x[(size_t)B_SZ * H_];
__device__ float g_parts[(size_t)B_SZ * 3 * D_];
__device__ float g_h[(size_t)B_SZ * H_];
__device__ float g_deter[(size_t)B_SZ * D_];
__device__ int   g_idx[B_SZ * K_];

// ---------------- helpers ----------------
__device__ __forceinline__ void cp_async16(void* smem_dst, const void* gmem_src) {
    unsigned s = (unsigned)__cvta_generic_to_shared(smem_dst);
    asm volatile("cp.async.ca.shared.global [%0], [%1], 16;\n" :: "r"(s), "l"(gmem_src));
}
__device__ __forceinline__ void cp_commit() { asm volatile("cp.async.commit_group;\n" ::: "memory"); }
__device__ __forceinline__ void cp_wait0()  { asm volatile("cp.async.wait_group 0;\n" ::: "memory"); }
__device__ __forceinline__ void ffma2(unsigned long long& acc, unsigned long long a,
                                      unsigned long long b) {
    asm volatile("fma.rn.f32x2 %0, %1, %2, %0;\n" : "+l"(acc) : "l"(a), "l"(b));
}
__device__ __forceinline__ unsigned long long dup_f32(float b) {
    unsigned long long u;
    asm("mov.b64 %0, {%1, %1};\n" : "=l"(u) : "f"(b));
    return u;
}
__device__ __forceinline__ float2 ull2f2(unsigned long long v) {
    float2 r;
    r.x = __uint_as_float((unsigned)(v & 0xffffffffull));
    r.y = __uint_as_float((unsigned)(v >> 32));
    return r;
}

// ================= SIMT fp32 SGEMM (bitwise-safe: per-element ascending-k chain) ===
// Retiling (BM/BN/TM/TN/MINB) changes scheduling only, never per-element rounding.
// EPI: 0=none, 1=+bias, 2=+bias,ELU, 3=+bias,+addmat,ELU
template<int BM, int BN, int BK, int TM, int TN, bool CONCAT, int EPI, int MINB>
__global__ void __launch_bounds__(256, MINB)
sgemm3_kernel(const float* __restrict__ A, const float* __restrict__ A2,
              const float* __restrict__ B, float* __restrict__ C,
              const float* __restrict__ bias, const float* __restrict__ addm,
              int M, int N, int K, int K1)
{
    constexpr int THREADS = (BM/TM)*(BN/TN);
    static_assert(THREADS == 256, "expect 256 threads");
    constexpr int AROW = BM + 4;
    extern __shared__ __align__(16) float smemf[];
    float* As = smemf;
    float* Bs = smemf + 2*BK*AROW;

    const int tid = threadIdx.x;
    const int tx  = tid % (BN/TN);
    const int ty  = tid / (BN/TN);
    const int bm  = blockIdx.y * BM;
    const int bn  = blockIdx.x * BN;

    constexpr int A_TPR = BK / 4;
    constexpr int A_RS  = THREADS / A_TPR;
    constexpr int A_IT  = BM / A_RS;
    const int a_r = tid / A_TPR;
    const int a_c = (tid % A_TPR) * 4;

    constexpr int B_TPR = BN / 4;
    constexpr int B_RS  = THREADS / B_TPR;
    constexpr int B_IT  = BK / B_RS;
    const int b_r = tid / B_TPR;
    const int b_c = (tid % B_TPR) * 4;

    float4 ar[A_IT];
    unsigned long long acc[TM/2][TN];
    #pragma unroll
    for (int i = 0; i < TM/2; ++i)
        #pragma unroll
        for (int j = 0; j < TN; ++j) acc[i][j] = 0ull;

    auto a_gload = [&](int kt) {
        const int k0 = kt * BK;
        #pragma unroll
        for (int i = 0; i < A_IT; ++i) {
            int gr = bm + a_r + i * A_RS;
            int gk = k0 + a_c;
            const float* src;
            if (CONCAT) {
                src = (gk < K1) ? (A  + (size_t)gr * K1       + gk)
                                : (A2 + (size_t)gr * (K - K1) + (gk - K1));
            } else {
                src = A + (size_t)gr * K + gk;
            }
            ar[i] = *(const float4*)src;
        }
    };
    auto a_sstore = [&](int bf) {
        float* base = As + (size_t)bf * BK * AROW;
        #pragma unroll
        for (int i = 0; i < A_IT; ++i) {
            int r = a_r + i * A_RS;
            base[(a_c + 0) * AROW + r] = ar[i].x;
            base[(a_c + 1) * AROW + r] = ar[i].y;
            base[(a_c + 2) * AROW + r] = ar[i].z;
            base[(a_c + 3) * AROW + r] = ar[i].w;
        }
    };
    auto b_gload = [&](int kt, int bf) {
        const int k0 = kt * BK;
        float* base = Bs + (size_t)bf * BK * BN;
        #pragma unroll
        for (int i = 0; i < B_IT; ++i) {
            int r = b_r + i * B_RS;
            cp_async16(base + r * BN + b_c, B + (size_t)(k0 + r) * N + bn + b_c);
        }
        cp_commit();
    };

    const int ntiles = K / BK;
    b_gload(0, 0);
    a_gload(0);
    a_sstore(0);
    cp_wait0();
    __syncthreads();

    int buf = 0;
    for (int kt = 0; kt < ntiles; ++kt) {
        if (kt + 1 < ntiles) {
            b_gload(kt + 1, buf ^ 1);
            a_gload(kt + 1);
        }
        const float* Asb = As + (size_t)buf * BK * AROW;
        const float* Bsb = Bs + (size_t)buf * BK * BN;
        #pragma unroll
        for (int kk = 0; kk < BK; ++kk) {
            unsigned long long apair[TM/2];
            #pragma unroll
            for (int i4 = 0; i4 < TM/4; ++i4) {
                ulonglong2 p = *(const ulonglong2*)(Asb + kk * AROW + ty * TM + 4 * i4);
                apair[2*i4]     = p.x;
                apair[2*i4 + 1] = p.y;
            }
            unsigned long long bdup[TN];
            #pragma unroll
            for (int j4 = 0; j4 < TN/4; ++j4) {
                float4 bv = *(const float4*)(Bsb + kk * BN + tx * TN + 4 * j4);
                bdup[4*j4 + 0] = dup_f32(bv.x);
                bdup[4*j4 + 1] = dup_f32(bv.y);
                bdup[4*j4 + 2] = dup_f32(bv.z);
                bdup[4*j4 + 3] = dup_f32(bv.w);
            }
            #pragma unroll
            for (int i = 0; i < TM/2; ++i)
                #pragma unroll
                for (int j = 0; j < TN; ++j)
                    ffma2(acc[i][j], apair[i], bdup[j]);
        }
        if (kt + 1 < ntiles) {
            a_sstore(buf ^ 1);
            cp_wait0();
        }
        __syncthreads();
        buf ^= 1;
    }

    #pragma unroll
    for (int i2 = 0; i2 < TM/2; ++i2) {
        int row0 = bm + ty * TM + 2 * i2;
        float lo[TN], hi[TN];
        #pragma unroll
        for (int j = 0; j < TN; ++j) {
            float2 v = ull2f2(acc[i2][j]);
            lo[j] = v.x; hi[j] = v.y;
        }
        #pragma unroll
        for (int half = 0; half < 2; ++half) {
            int row = row0 + half;
            float* vals = half ? hi : lo;
            #pragma unroll
            for (int j = 0; j < TN; ++j) {
                int col = bn + tx * TN + j;
                float v = vals[j];
                if (EPI >= 1) v += bias[col];
                if (EPI == 3) v += addm[(size_t)row * N + col];
                if (EPI >= 2) v = (v > 0.f) ? v : expm1f(v);
                vals[j] = v;
            }
            #pragma unroll
            for (int j4 = 0; j4 < TN/4; ++j4)
                *(float4*)(C + (size_t)row * N + bn + tx * TN + 4 * j4) =
                    *(const float4*)(vals + 4 * j4);
        }
    }
}

template<int BM, int BN, int BK, int TM, int TN, bool CONCAT, int EPI, int MINB>
static void launch_sgemm3(const float* A, const float* A2, const float* B, float* C,
                          const float* bias, const float* addm,
                          int M, int N, int K, int K1)
{
    constexpr int AROW = BM + 4;
    constexpr size_t SMEM = (size_t)(2*BK*AROW + 2*BK*BN) * sizeof(float);
    cudaFuncSetAttribute((const void*)sgemm3_kernel<BM,BN,BK,TM,TN,CONCAT,EPI,MINB>,
                         cudaFuncAttributeMaxDynamicSharedMemorySize, (int)SMEM);
    dim3 g(N / BN, M / BM);
    sgemm3_kernel<BM,BN,BK,TM,TN,CONCAT,EPI,MINB><<<g, 256, SMEM>>>(
        A, A2, B, C, bias, addm, M, N, K, K1);
}

// ---------------- x = elu(ae + b_is + one-hot gather of W_is) ----------------
__global__ void x_gather_kernel(const float* __restrict__ ae, const float* __restrict__ b_is,
                                const float* __restrict__ W_is, const int* __restrict__ idx,
                                float* __restrict__ x)
{
    int j = blockIdx.x * blockDim.x + threadIdx.x;
    int b = blockIdx.y;
    __shared__ int sid[K_];
    if (threadIdx.x < K_) sid[threadIdx.x] = idx[b * K_ + threadIdx.x];
    __syncthreads();
    float v = ae[(size_t)b * H_ + j] + b_is[j];
    #pragma unroll
    for (int k = 0; k < K_; ++k)
        v += W_is[(size_t)sid[k] * H_ + j];
    x[(size_t)b * H_ + j] = (v > 0.f) ? v : expm1f(v);
}

// ---------------- fused LayerNorm(6144) + GRU gates + deter update ----------------
// VERBATIM R4 body — reciprocal-multiply mean/var (NOT division): this single
// rounding difference was flipping one gumbel argmax in R9-R13.
__global__ void ln_gru_kernel(const float* __restrict__ parts,
                              const float* __restrict__ ln_g,
                              const float* __restrict__ ln_b,
                              float* __restrict__ deter,
                              float* __restrict__ deters_out)
{
    const int row = blockIdx.x;
    const float* p = parts + (size_t)row * (3 * D_);
    float s = 0.f, s2 = 0.f;
    for (int i = threadIdx.x * 4; i < 3 * D_; i += 256 * 4) {
        float4 v = *(const float4*)(p + i);
        s  += v.x + v.y + v.z + v.w;
        s2 += v.x * v.x + v.y * v.y + v.z * v.z + v.w * v.w;
    }
    __shared__ float shs[8], shs2[8];
    #pragma unroll
    for (int off = 16; off > 0; off >>= 1) {
        s  += __shfl_down_sync(0xffffffffu, s,  off);
        s2 += __shfl_down_sync(0xffffffffu, s2, off);
    }
    int warp = threadIdx.x >> 5, lane = threadIdx.x & 31;
    if (lane == 0) { shs[warp] = s; shs2[warp] = s2; }
    __syncthreads();
    __shared__ float sh_m, sh_rstd;
    if (threadIdx.x == 0) {
        float S = 0.f, S2 = 0.f;
        #pragma unroll
        for (int i = 0; i < 8; ++i) { S += shs[i]; S2 += shs2[i]; }
        float m   = S * (1.f / (3 * D_));
        float var = S2 * (1.f / (3 * D_)) - m * m;
        sh_m = m; sh_rstd = rsqrtf(var + 1e-5f);
    }
    __syncthreads();
    const float m = sh_m, rstd = sh_rstd;
    for (int j = threadIdx.x; j < D_; j += 256) {
        float r = (p[j]          - m) * rstd * ln_g[j]          + ln_b[j];
        float c = (p[j + D_]     - m) * rstd * ln_g[j + D_]     + ln_b[j + D_];
        float u = (p[j + 2 * D_] - m) * rstd * ln_g[j + 2 * D_] + ln_b[j + 2 * D_];
        float sr   = 1.f / (1.f + expf(-r));
        float cand = tanhf(sr * c);
        float up   = 1.f / (1.f + expf(-(u - 1.f)));
        float dprev = deter[(size_t)row * D_ + j];
        float dn = up * cand + (1.f - up) * dprev;
        deter[(size_t)row * D_ + j] = dn;
        deters_out[(size_t)row * D_ + j] = dn;
    }
}

// ---------------- gumbel-max sampling: one warp per (b,k) ----------------
__global__ void sample_kernel(const float* __restrict__ logits,
                              const float* __restrict__ unif,
                              int* __restrict__ idx_out,
                              float* __restrict__ stochs_out)
{
    int gw   = (blockIdx.x * blockDim.x + threadIdx.x) >> 5;
    int lane = threadIdx.x & 31;
    size_t base = (size_t)gw * V_ + lane;
    float logit = logits[base];
    float u = unif[base];
    u = fminf(fmaxf(u, 1e-5f), 1.0f - 1e-5f);
    float val = logit - logf(-logf(u));
    int idx = lane;
    #pragma unroll
    for (int off = 16; off > 0; off >>= 1) {
        float ov = __shfl_down_sync(0xffffffffu, val, off);
        int   oi = __shfl_down_sync(0xffffffffu, idx, off);
        if (ov > val || (ov == val && oi < idx)) { val = ov; idx = oi; }
    }
    idx = __shfl_sync(0xffffffffu, idx, 0);
    stochs_out[base] = (lane == idx) ? 1.0f : 0.0f;
    if (lane == 0) idx_out[gw] = ((gw & (K_ - 1)) << 5) | idx;
}

#define GSA(p, s) cudaGetSymbolAddress((void**)&p, s)

extern "C" void kernel_launch(void* const* d_in, const int* in_sizes, int n_in,
                              void* d_out, int out_size)
{
    (void)in_sizes; (void)n_in; (void)out_size;
    const float* obs    = (const float*)d_in[0];
    const float* act    = (const float*)d_in[1];
    const float* deter0 = (const float*)d_in[2];
    const float* stoch0 = (const float*)d_in[3];
    const float* unif   = (const float*)d_in[4];
    const float* W_oo = (const float*)d_in[5];  const float* b_oo = (const float*)d_in[6];
    const float* W_ia = (const float*)d_in[7];  const float* b_ia = (const float*)d_in[8];
    const float* W_is = (const float*)d_in[9];  const float* b_is = (const float*)d_in[10];
    const float* W_gru = (const float*)d_in[11];
    const float* ln_g = (const float*)d_in[12]; const float* ln_b = (const float*)d_in[13];
    const float* W_od = (const float*)d_in[14]; const float* b_od = (const float*)d_in[15];
    const float* W_op = (const float*)d_in[16]; const float* b_op = (const float*)d_in[17];
    const float* W_io = (const float*)d_in[18]; const float* b_io = (const float*)d_in[19];
    const float* W_ip = (const float*)d_in[20]; const float* b_ip = (const float*)d_in[21];

    float* out = (float*)d_out;
    float* deters = out;
    float* stochs = deters + (size_t)TB * D_;
    float* posts  = stochs + (size_t)TB * S_;
    float* priors = posts  + (size_t)TB * S_;

    float *obs_e, *act_e, *xbuf, *parts, *hbuf, *deter; int* idxb;
    GSA(obs_e, g_obs_e); GSA(act_e, g_act_e); GSA(xbuf, g_x);
    GSA(parts, g_parts); GSA(hbuf, g_h); GSA(deter, g_deter); GSA(idxb, g_idx);

    cudaMemcpyAsync(deter, deter0, (size_t)SL * sizeof(float), cudaMemcpyDeviceToDevice, 0);

    // pre-GEMMs (R4-bitwise configs)
    launch_sgemm3<128,128,16,8,8,false,1,2>(obs, nullptr, W_oo, obs_e, b_oo, nullptr,
                                            TB, H_, OBS_, 0);
    launch_sgemm3<128,128,16,8,8,false,1,2>(act, nullptr, W_ia, act_e, b_ia, nullptr,
                                            TB, H_, ACT_, 0);

    for (int t = 0; t < T_STEPS; ++t) {
        const float* ae = act_e + (size_t)t * B_SZ * H_;
        const float* oe = obs_e + (size_t)t * B_SZ * H_;
        if (t == 0) {
            launch_sgemm3<64,128,16,4,8,false,3,3>(stoch0, nullptr, W_is, xbuf, b_is, ae,
                                                   B_SZ, H_, S_, 0);
        } else {
            dim3 g(H_ / 256, B_SZ);
            x_gather_kernel<<<g, 256>>>(ae, b_is, W_is, idxb, xbuf);
        }
        // GRU: 64x128 tile, 3 CTAs/SM -> 384 CTAs resident (bitwise-equal retile)
        launch_sgemm3<64,128,16,4,8,true,0,3>(xbuf, deter, W_gru, parts, nullptr, nullptr,
                                              B_SZ, 3 * D_, H_ + D_, H_);
        ln_gru_kernel<<<B_SZ, 256>>>(parts, ln_g, ln_b, deter,
                                     deters + (size_t)t * SL);
        // W_od: 64x64 tile, 4 CTAs/SM -> 256 CTAs (bitwise-equal retile)
        launch_sgemm3<64,64,16,4,4,false,3,4>(deter, nullptr, W_od, hbuf, b_od, oe,
                                              B_SZ, H_, D_, 0);
        launch_sgemm3<64,64,16,4,4,false,1,4>(hbuf, nullptr, W_op,
                                              posts + (size_t)t * B_SZ * S_, b_op, nullptr,
                                              B_SZ, S_, H_, 0);
        sample_kernel<<<(B_SZ * K_ * 32) / 256, 256>>>(
            posts + (size_t)t * B_SZ * S_, unif + (size_t)t * B_SZ * K_ * V_,
            idxb, stochs + (size_t)t * B_SZ * S_);
    }

    // priors: R4-bitwise SIMT fp32 path (act_e reused as hidden scratch)
    launch_sgemm3<128,128,16,8,8,false,2,2>(deters, nullptr, W_io, act_e, b_io, nullptr,
                                            TB, H_, D_, 0);
    launch_sgemm3<128,128,16,8,8,false,1,2>(act_e, nullptr, W_ip, priors, b_ip, nullptr,
                                            TB, S_, H_, 0);
}

// round 16
// speedup vs baseline: 1.1545x; 1.1545x over previous
#include <cuda_runtime.h>
#include <cuda_bf16.h>
#include <math.h>
#include <stdint.h>

#define T_STEPS 64
#define B_SZ    512
#define OBS_    1536
#define ACT_    32
#define D_      2048
#define H_      2048
#define K_      32
#define V_      32
#define S_      1024
#define SL      (B_SZ * D_)
#define TB      (T_STEPS * B_SZ)
typedef __nv_bfloat16 bf16;

// ---------------- device scratch ----------------
__device__ float g_obs_e[(size_t)TB * H_];
__device__ float g_act_e[(size_t)TB * H_];
__device__ float g_x[(size_t)B_SZ * H_];
__device__ float g_parts[(size_t)B_SZ * 3 * D_];
__device__ float g_h[(size_t)B_SZ * H_];
__device__ float g_deter[(size_t)B_SZ * D_];
__device__ int   g_idx[B_SZ * K_];
// priors TC path
__device__ bf16 g_dsp[3 * (size_t)TB * D_];
__device__ bf16 g_php[3 * (size_t)TB * H_];
__device__ bf16 g_Wio_s[3 * (size_t)H_ * D_];
__device__ bf16 g_Wip_s[3 * (size_t)S_ * H_];

// ---------------- helpers ----------------
__device__ __forceinline__ uint32_t smem_u32(const void* p) {
    uint32_t a;
    asm("{ .reg .u64 t; cvta.to.shared.u64 t, %1; cvt.u32.u64 %0, t; }" : "=r"(a) : "l"(p));
    return a;
}
__device__ __forceinline__ void cp_async16(void* smem_dst, const void* gmem_src) {
    unsigned s = (unsigned)__cvta_generic_to_shared(smem_dst);
    asm volatile("cp.async.ca.shared.global [%0], [%1], 16;\n" :: "r"(s), "l"(gmem_src));
}
__device__ __forceinline__ void cp16(uint32_t dst, const void* src) {
    asm volatile("cp.async.cg.shared.global [%0], [%1], 16;\n" :: "r"(dst), "l"(src));
}
__device__ __forceinline__ void cp_commit() { asm volatile("cp.async.commit_group;\n" ::: "memory"); }
__device__ __forceinline__ void cp_wait1()  { asm volatile("cp.async.wait_group 1;\n" ::: "memory"); }
__device__ __forceinline__ void cp_wait0()  { asm volatile("cp.async.wait_group 0;\n" ::: "memory"); }
__device__ __forceinline__ void ffma2(unsigned long long& acc, unsigned long long a,
                                      unsigned long long b) {
    asm volatile("fma.rn.f32x2 %0, %1, %2, %0;\n" : "+l"(acc) : "l"(a), "l"(b));
}
__device__ __forceinline__ unsigned long long dup_f32(float b) {
    unsigned long long u;
    asm("mov.b64 %0, {%1, %1};\n" : "=l"(u) : "f"(b));
    return u;
}
__device__ __forceinline__ float2 ull2f2(unsigned long long v) {
    float2 r;
    r.x = __uint_as_float((unsigned)(v & 0xffffffffull));
    r.y = __uint_as_float((unsigned)(v >> 32));
    return r;
}
__device__ __forceinline__ uint4 ldmx4(uint32_t a) {
    uint4 v;
    asm volatile("ldmatrix.sync.aligned.m8n8.x4.shared.b16 {%0,%1,%2,%3}, [%4];"
                 : "=r"(v.x), "=r"(v.y), "=r"(v.z), "=r"(v.w) : "r"(a));
    return v;
}
__device__ __forceinline__ void mma_bf16(float* c, const uint4& a, uint32_t b0, uint32_t b1) {
    asm volatile("mma.sync.aligned.m16n8k16.row.col.f32.bf16.bf16.f32 "
        "{%0,%1,%2,%3}, {%4,%5,%6,%7}, {%8,%9}, {%0,%1,%2,%3};"
        : "+f"(c[0]), "+f"(c[1]), "+f"(c[2]), "+f"(c[3])
        : "r"(a.x), "r"(a.y), "r"(a.z), "r"(a.w), "r"(b0), "r"(b1));
}
__device__ __forceinline__ void bf16_split3(float x, bf16& h, bf16& m, bf16& l) {
    h = __float2bfloat16_rn(x);
    float r = x - __bfloat162float(h);
    m = __float2bfloat16_rn(r);
    r -= __bfloat162float(m);
    l = __float2bfloat16_rn(r);
}

// ================= SIMT fp32 SGEMM (R4-bitwise; decision path) =====================
// EPI: 0=none, 1=+bias, 2=+bias,ELU, 3=+bias,+addmat,ELU
template<int BM, int BN, int BK, int TM, int TN, bool CONCAT, int EPI>
__global__ void __launch_bounds__(256, 2)
sgemm3_kernel(const float* __restrict__ A, const float* __restrict__ A2,
              const float* __restrict__ B, float* __restrict__ C,
              const float* __restrict__ bias, const float* __restrict__ addm,
              int M, int N, int K, int K1)
{
    constexpr int THREADS = (BM/TM)*(BN/TN);
    static_assert(THREADS == 256, "expect 256 threads");
    constexpr int AROW = BM + 4;
    extern __shared__ __align__(16) float smemf[];
    float* As = smemf;
    float* Bs = smemf + 2*BK*AROW;

    const int tid = threadIdx.x;
    const int tx  = tid % (BN/TN);
    const int ty  = tid / (BN/TN);
    const int bm  = blockIdx.y * BM;
    const int bn  = blockIdx.x * BN;

    constexpr int A_TPR = BK / 4;
    constexpr int A_RS  = THREADS / A_TPR;
    constexpr int A_IT  = BM / A_RS;
    const int a_r = tid / A_TPR;
    const int a_c = (tid % A_TPR) * 4;

    constexpr int B_TPR = BN / 4;
    constexpr int B_RS  = THREADS / B_TPR;
    constexpr int B_IT  = BK / B_RS;
    const int b_r = tid / B_TPR;
    const int b_c = (tid % B_TPR) * 4;

    float4 ar[A_IT];
    unsigned long long acc[TM/2][TN];
    #pragma unroll
    for (int i = 0; i < TM/2; ++i)
        #pragma unroll
        for (int j = 0; j < TN; ++j) acc[i][j] = 0ull;

    auto a_gload = [&](int kt) {
        const int k0 = kt * BK;
        #pragma unroll
        for (int i = 0; i < A_IT; ++i) {
            int gr = bm + a_r + i * A_RS;
            int gk = k0 + a_c;
            const float* src;
            if (CONCAT) {
                src = (gk < K1) ? (A  + (size_t)gr * K1       + gk)
                                : (A2 + (size_t)gr * (K - K1) + (gk - K1));
            } else {
                src = A + (size_t)gr * K + gk;
            }
            ar[i] = *(const float4*)src;
        }
    };
    auto a_sstore = [&](int bf) {
        float* base = As + (size_t)bf * BK * AROW;
        #pragma unroll
        for (int i = 0; i < A_IT; ++i) {
            int r = a_r + i * A_RS;
            base[(a_c + 0) * AROW + r] = ar[i].x;
            base[(a_c + 1) * AROW + r] = ar[i].y;
            base[(a_c + 2) * AROW + r] = ar[i].z;
            base[(a_c + 3) * AROW + r] = ar[i].w;
        }
    };
    auto b_gload = [&](int kt, int bf) {
        const int k0 = kt * BK;
        float* base = Bs + (size_t)bf * BK * BN;
        #pragma unroll
        for (int i = 0; i < B_IT; ++i) {
            int r = b_r + i * B_RS;
            cp_async16(base + r * BN + b_c, B + (size_t)(k0 + r) * N + bn + b_c);
        }
        cp_commit();
    };

    const int ntiles = K / BK;
    b_gload(0, 0);
    a_gload(0);
    a_sstore(0);
    cp_wait0();
    __syncthreads();

    int buf = 0;
    for (int kt = 0; kt < ntiles; ++kt) {
        if (kt + 1 < ntiles) {
            b_gload(kt + 1, buf ^ 1);
            a_gload(kt + 1);
        }
        const float* Asb = As + (size_t)buf * BK * AROW;
        const float* Bsb = Bs + (size_t)buf * BK * BN;
        #pragma unroll
        for (int kk = 0; kk < BK; ++kk) {
            unsigned long long apair[TM/2];
            #pragma unroll
            for (int i4 = 0; i4 < TM/4; ++i4) {
                ulonglong2 p = *(const ulonglong2*)(Asb + kk * AROW + ty * TM + 4 * i4);
                apair[2*i4]     = p.x;
                apair[2*i4 + 1] = p.y;
            }
            unsigned long long bdup[TN];
            #pragma unroll
            for (int j4 = 0; j4 < TN/4; ++j4) {
                float4 bv = *(const float4*)(Bsb + kk * BN + tx * TN + 4 * j4);
                bdup[4*j4 + 0] = dup_f32(bv.x);
                bdup[4*j4 + 1] = dup_f32(bv.y);
                bdup[4*j4 + 2] = dup_f32(bv.z);
                bdup[4*j4 + 3] = dup_f32(bv.w);
            }
            #pragma unroll
            for (int i = 0; i < TM/2; ++i)
                #pragma unroll
                for (int j = 0; j < TN; ++j)
                    ffma2(acc[i][j], apair[i], bdup[j]);
        }
        if (kt + 1 < ntiles) {
            a_sstore(buf ^ 1);
            cp_wait0();
        }
        __syncthreads();
        buf ^= 1;
    }

    #pragma unroll
    for (int i2 = 0; i2 < TM/2; ++i2) {
        int row0 = bm + ty * TM + 2 * i2;
        float lo[TN], hi[TN];
        #pragma unroll
        for (int j = 0; j < TN; ++j) {
            float2 v = ull2f2(acc[i2][j]);
            lo[j] = v.x; hi[j] = v.y;
        }
        #pragma unroll
        for (int half = 0; half < 2; ++half) {
            int row = row0 + half;
            float* vals = half ? hi : lo;
            #pragma unroll
            for (int j = 0; j < TN; ++j) {
                int col = bn + tx * TN + j;
                float v = vals[j];
                if (EPI >= 1) v += bias[col];
                if (EPI == 3) v += addm[(size_t)row * N + col];
                if (EPI >= 2) v = (v > 0.f) ? v : expm1f(v);
                vals[j] = v;
            }
            #pragma unroll
            for (int j4 = 0; j4 < TN/4; ++j4)
                *(float4*)(C + (size_t)row * N + bn + tx * TN + 4 * j4) =
                    *(const float4*)(vals + 4 * j4);
        }
    }
}

template<int BM, int BN, int BK, int TM, int TN, bool CONCAT, int EPI>
static void launch_sgemm3(const float* A, const float* A2, const float* B, float* C,
                          const float* bias, const float* addm,
                          int M, int N, int K, int K1)
{
    constexpr int AROW = BM + 4;
    constexpr size_t SMEM = (size_t)(2*BK*AROW + 2*BK*BN) * sizeof(float);
    cudaFuncSetAttribute((const void*)sgemm3_kernel<BM,BN,BK,TM,TN,CONCAT,EPI>,
                         cudaFuncAttributeMaxDynamicSharedMemorySize, (int)SMEM);
    dim3 g(N / BN, M / BM);
    sgemm3_kernel<BM,BN,BK,TM,TN,CONCAT,EPI><<<g, 256, SMEM>>>(
        A, A2, B, C, bias, addm, M, N, K, K1);
}

// ================= bf16x6 dual-acc TC GEMM (priors only; NPROD=6) =================
#define MM_SMEM 196608

template<int EPI, bool WC, bool SO>
__global__ void __launch_bounds__(256)
mm_gemm(const bf16* __restrict__ A0, size_t aps0,
        const bf16* __restrict__ Bt,
        float* __restrict__ C, const float* __restrict__ bias,
        bf16* __restrict__ Co, size_t cps,
        int M, int N, int K)
{
    extern __shared__ __align__(16) char smem[];
    const uint32_t sb = smem_u32(smem);
    const int tid = threadIdx.x;
    const int w = tid >> 5, lane = tid & 31;
    const int gid = lane >> 2, tig = lane & 3;
    const int wm = w >> 1, wn = w & 1;
    const int bm = blockIdx.y * 128, bn = blockIdx.x * 128;
    const int NT = K / 64;
    const size_t bps = (size_t)N * K;

    float acc1[2][8][4], acc2[2][8][4];
    #pragma unroll
    for (int i = 0; i < 2; ++i)
        #pragma unroll
        for (int j = 0; j < 8; ++j)
            #pragma unroll
            for (int q = 0; q < 4; ++q) { acc1[i][j][q] = 0.f; acc2[i][j][q] = 0.f; }

    auto load_tile = [&](int kt, int s) {
        uint32_t ab = sb + s * 98304u;
        #pragma unroll
        for (int i = 0; i < 12; ++i) {
            int id = tid + 256 * i;
            int p = id >> 10, rem = id & 1023;
            int row = rem >> 3, ch = rem & 7;
            uint32_t off = (uint32_t)(p * 16384 + row * 128 + ((ch ^ (row & 7)) * 16));
            cp16(ab + off, A0 + p * aps0 + (size_t)(bm + row) * K + kt * 64 + ch * 8);
            cp16(ab + 49152u + off, Bt + p * bps + (size_t)(bn + row) * K + kt * 64 + ch * 8);
        }
        cp_commit();
    };

    const int a_roff = lane & 15;
    const int a_csel = lane >> 4;
    const int b_roff = (lane & 7) + ((lane >> 4) << 3);
    const int b_csel = (lane >> 3) & 1;

    load_tile(0, 0);
    for (int kt = 0; kt < NT; ++kt) {
        int s = kt & 1;
        if (kt + 1 < NT) load_tile(kt + 1, s ^ 1);
        if (kt + 1 < NT) cp_wait1(); else cp_wait0();
        __syncthreads();
        uint32_t ab = sb + s * 98304u, bb = ab + 49152u;
        #pragma unroll
        for (int g = 0; g < 4; ++g) {
            uint4 aF[3][2];
            #pragma unroll
            for (int p = 0; p < 3; ++p)
                #pragma unroll
                for (int mi = 0; mi < 2; ++mi) {
                    int r = wm * 32 + mi * 16 + a_roff;
                    int ch = 2 * g + a_csel;
                    aF[p][mi] = ldmx4(ab + p * 16384u +
                        (uint32_t)(r * 128 + ((ch ^ (r & 7)) * 16)));
                }
            #pragma unroll
            for (int no = 0; no < 4; ++no) {
                int r = wn * 64 + no * 16 + b_roff;
                int ch = 2 * g + b_csel;
                uint32_t boff = (uint32_t)(r * 128 + ((ch ^ (r & 7)) * 16));
                uint4 bH = ldmx4(bb + boff);
                uint4 bM = ldmx4(bb + 16384u + boff);
                uint4 bL = ldmx4(bb + 32768u + boff);
                #pragma unroll
                for (int half = 0; half < 2; ++half) {
                    int ni = 2 * no + half;
                    uint32_t h0 = half ? bH.z : bH.x, h1 = half ? bH.w : bH.y;
                    uint32_t m0 = half ? bM.z : bM.x, m1 = half ? bM.w : bM.y;
                    uint32_t l0 = half ? bL.z : bL.x, l1 = half ? bL.w : bL.y;
                    #pragma unroll
                    for (int mi = 0; mi < 2; ++mi) {
                        mma_bf16(acc1[mi][ni], aF[0][mi], h0, h1);   // hh -> main
                        mma_bf16(acc2[mi][ni], aF[0][mi], m0, m1);   // hm
                        mma_bf16(acc2[mi][ni], aF[1][mi], h0, h1);   // mh
                        mma_bf16(acc2[mi][ni], aF[0][mi], l0, l1);   // hl
                        mma_bf16(acc2[mi][ni], aF[2][mi], h0, h1);   // lh
                        mma_bf16(acc2[mi][ni], aF[1][mi], m0, m1);   // mm
                    }
                }
            }
        }
        __syncthreads();
    }

    #pragma unroll
    for (int mi = 0; mi < 2; ++mi)
        #pragma unroll
        for (int ni = 0; ni < 8; ++ni) {
            int col = bn + wn * 64 + ni * 8 + 2 * tig;
            #pragma unroll
            for (int hf = 0; hf < 2; ++hf) {
                int row = bm + wm * 32 + mi * 16 + gid + hf * 8;
                float v0 = acc1[mi][ni][2 * hf]     + acc2[mi][ni][2 * hf];
                float v1 = acc1[mi][ni][2 * hf + 1] + acc2[mi][ni][2 * hf + 1];
                if (EPI >= 1) { v0 += bias[col]; v1 += bias[col + 1]; }
                if (EPI >= 2) {
                    v0 = (v0 > 0.f) ? v0 : expm1f(v0);
                    v1 = (v1 > 0.f) ? v1 : expm1f(v1);
                }
                if (WC)
                    *(float2*)(C + (size_t)row * N + col) = make_float2(v0, v1);
                if (SO) {
                    bf16 h, m, l;
                    size_t p0 = (size_t)row * N + col;
                    bf16_split3(v0, h, m, l);
                    Co[p0] = h; Co[cps + p0] = m; Co[2 * cps + p0] = l;
                    bf16_split3(v1, h, m, l);
                    Co[p0 + 1] = h; Co[cps + p0 + 1] = m; Co[2 * cps + p0 + 1] = l;
                }
            }
        }
}

template<int EPI, bool WC, bool SO>
static void launch_mm(const bf16* A0, size_t aps0, const bf16* Bt, float* C,
                      const float* bias, bf16* Co, size_t cps, int M, int N, int K)
{
    cudaFuncSetAttribute((const void*)mm_gemm<EPI, WC, SO>,
                         cudaFuncAttributeMaxDynamicSharedMemorySize, MM_SMEM);
    dim3 g(N / 128, M / 128);
    mm_gemm<EPI, WC, SO><<<g, 256, MM_SMEM>>>(A0, aps0, Bt, C, bias, Co, cps, M, N, K);
}

// ---------------- bf16 preprocessing (priors path only) ----------------
__global__ void tsplit_kernel(const float* __restrict__ W, bf16* __restrict__ T,
                              int Kd, int Nd)
{
    __shared__ float t[32][33];
    int n0 = blockIdx.x * 32, k0 = blockIdx.y * 32;
    for (int i = threadIdx.y; i < 32; i += 8)
        t[i][threadIdx.x] = W[(size_t)(k0 + i) * Nd + n0 + threadIdx.x];
    __syncthreads();
    size_t ps = (size_t)Nd * Kd;
    for (int i = threadIdx.y; i < 32; i += 8) {
        bf16 h, m, l;
        bf16_split3(t[threadIdx.x][i], h, m, l);
        size_t pos = (size_t)(n0 + i) * Kd + k0 + threadIdx.x;
        T[pos] = h; T[ps + pos] = m; T[2 * ps + pos] = l;
    }
}
__global__ void split_kernel(const float* __restrict__ X, bf16* __restrict__ O,
                             size_t ps, int F)
{
    int j = blockIdx.x * 256 + threadIdx.x;
    if (j >= F) return;
    size_t row = blockIdx.y;
    bf16 h, m, l;
    bf16_split3(X[row * F + j], h, m, l);
    size_t pos = row * F + j;
    O[pos] = h; O[ps + pos] = m; O[2 * ps + pos] = l;
}

// ---------------- x = elu(ae + b_is + one-hot gather of W_is) ----------------
__global__ void x_gather_kernel(const float* __restrict__ ae, const float* __restrict__ b_is,
                                const float* __restrict__ W_is, const int* __restrict__ idx,
                                float* __restrict__ x)
{
    int j = blockIdx.x * blockDim.x + threadIdx.x;
    int b = blockIdx.y;
    __shared__ int sid[K_];
    if (threadIdx.x < K_) sid[threadIdx.x] = idx[b * K_ + threadIdx.x];
    __syncthreads();
    float v = ae[(size_t)b * H_ + j] + b_is[j];
    #pragma unroll
    for (int k = 0; k < K_; ++k)
        v += W_is[(size_t)sid[k] * H_ + j];
    x[(size_t)b * H_ + j] = (v > 0.f) ? v : expm1f(v);
}

// ---------------- fused LayerNorm + GRU gates (R4-verbatim numerics) ----------------
__global__ void ln_gru_kernel(const float* __restrict__ parts,
                              const float* __restrict__ ln_g,
                              const float* __restrict__ ln_b,
                              float* __restrict__ deter,
                              float* __restrict__ deters_out)
{
    const int row = blockIdx.x;
    const float* p = parts + (size_t)row * (3 * D_);
    float s = 0.f, s2 = 0.f;
    for (int i = threadIdx.x * 4; i < 3 * D_; i += 256 * 4) {
        float4 v = *(const float4*)(p + i);
        s  += v.x + v.y + v.z + v.w;
        s2 += v.x * v.x + v.y * v.y + v.z * v.z + v.w * v.w;
    }
    __shared__ float shs[8], shs2[8];
    #pragma unroll
    for (int off = 16; off > 0; off >>= 1) {
        s  += __shfl_down_sync(0xffffffffu, s,  off);
        s2 += __shfl_down_sync(0xffffffffu, s2, off);
    }
    int warp = threadIdx.x >> 5, lane = threadIdx.x & 31;
    if (lane == 0) { shs[warp] = s; shs2[warp] = s2; }
    __syncthreads();
    __shared__ float sh_m, sh_rstd;
    if (threadIdx.x == 0) {
        float S = 0.f, S2 = 0.f;
        #pragma unroll
        for (int i = 0; i < 8; ++i) { S += shs[i]; S2 += shs2[i]; }
        float m   = S * (1.f / (3 * D_));
        float var = S2 * (1.f / (3 * D_)) - m * m;
        sh_m = m; sh_rstd = rsqrtf(var + 1e-5f);
    }
    __syncthreads();
    const float m = sh_m, rstd = sh_rstd;
    for (int j = threadIdx.x; j < D_; j += 256) {
        float r = (p[j]          - m) * rstd * ln_g[j]          + ln_b[j];
        float c = (p[j + D_]     - m) * rstd * ln_g[j + D_]     + ln_b[j + D_];
        float u = (p[j + 2 * D_] - m) * rstd * ln_g[j + 2 * D_] + ln_b[j + 2 * D_];
        float sr   = 1.f / (1.f + expf(-r));
        float cand = tanhf(sr * c);
        float up   = 1.f / (1.f + expf(-(u - 1.f)));
        float dprev = deter[(size_t)row * D_ + j];
        float dn = up * cand + (1.f - up) * dprev;
        deter[(size_t)row * D_ + j] = dn;
        deters_out[(size_t)row * D_ + j] = dn;
    }
}

// ---------------- gumbel-max sampling ----------------
__global__ void sample_kernel(const float* __restrict__ logits,
                              const float* __restrict__ unif,
                              int* __restrict__ idx_out,
                              float* __restrict__ stochs_out)
{
    int gw   = (blockIdx.x * blockDim.x + threadIdx.x) >> 5;
    int lane = threadIdx.x & 31;
    size_t base = (size_t)gw * V_ + lane;
    float logit = logits[base];
    float u = unif[base];
    u = fminf(fmaxf(u, 1e-5f), 1.0f - 1e-5f);
    float val = logit - logf(-logf(u));
    int idx = lane;
    #pragma unroll
    for (int off = 16; off > 0; off >>= 1) {
        float ov = __shfl_down_sync(0xffffffffu, val, off);
        int   oi = __shfl_down_sync(0xffffffffu, idx, off);
        if (ov > val || (ov == val && oi < idx)) { val = ov; idx = oi; }
    }
    idx = __shfl_sync(0xffffffffu, idx, 0);
    stochs_out[base] = (lane == idx) ? 1.0f : 0.0f;
    if (lane == 0) idx_out[gw] = ((gw & (K_ - 1)) << 5) | idx;
}

#define GSA(p, s) cudaGetSymbolAddress((void**)&p, s)

extern "C" void kernel_launch(void* const* d_in, const int* in_sizes, int n_in,
                              void* d_out, int out_size)
{
    (void)in_sizes; (void)n_in; (void)out_size;
    const float* obs    = (const float*)d_in[0];
    const float* act    = (const float*)d_in[1];
    const float* deter0 = (const float*)d_in[2];
    const float* stoch0 = (const float*)d_in[3];
    const float* unif   = (const float*)d_in[4];
    const float* W_oo = (const float*)d_in[5];  const float* b_oo = (const float*)d_in[6];
    const float* W_ia = (const float*)d_in[7];  const float* b_ia = (const float*)d_in[8];
    const float* W_is = (const float*)d_in[9];  const float* b_is = (const float*)d_in[10];
    const float* W_gru = (const float*)d_in[11];
    const float* ln_g = (const float*)d_in[12]; const float* ln_b = (const float*)d_in[13];
    const float* W_od = (const float*)d_in[14]; const float* b_od = (const float*)d_in[15];
    const float* W_op = (const float*)d_in[16]; const float* b_op = (const float*)d_in[17];
    const float* W_io = (const float*)d_in[18]; const float* b_io = (const float*)d_in[19];
    const float* W_ip = (const float*)d_in[20]; const float* b_ip = (const float*)d_in[21];

    float* out = (float*)d_out;
    float* deters = out;
    float* stochs = deters + (size_t)TB * D_;
    float* posts  = stochs + (size_t)TB * S_;
    float* priors = posts  + (size_t)TB * S_;

    float *obs_e, *act_e, *xbuf, *parts, *hbuf, *deter; int* idxb;
    bf16 *dsp, *php, *Wio_s, *Wip_s;
    GSA(obs_e, g_obs_e); GSA(act_e, g_act_e); GSA(xbuf, g_x);
    GSA(parts, g_parts); GSA(hbuf, g_h); GSA(deter, g_deter); GSA(idxb, g_idx);
    GSA(dsp, g_dsp); GSA(php, g_php); GSA(Wio_s, g_Wio_s); GSA(Wip_s, g_Wip_s);

    cudaMemcpyAsync(deter, deter0, (size_t)SL * sizeof(float), cudaMemcpyDeviceToDevice, 0);

    // priors weight splits (off the decision path)
    { dim3 g(H_ / 32, D_ / 32); tsplit_kernel<<<g, dim3(32, 8)>>>(W_io, Wio_s, D_, H_); }
    { dim3 g(S_ / 32, H_ / 32); tsplit_kernel<<<g, dim3(32, 8)>>>(W_ip, Wip_s, H_, S_); }

    // ======= decision path: R4 bitwise verbatim =======
    launch_sgemm3<128,128,16,8,8,false,1>(obs, nullptr, W_oo, obs_e, b_oo, nullptr,
                                          TB, H_, OBS_, 0);
    launch_sgemm3<128,128,16,8,8,false,1>(act, nullptr, W_ia, act_e, b_ia, nullptr,
                                          TB, H_, ACT_, 0);

    for (int t = 0; t < T_STEPS; ++t) {
        const float* ae = act_e + (size_t)t * B_SZ * H_;
        const float* oe = obs_e + (size_t)t * B_SZ * H_;
        if (t == 0) {
            launch_sgemm3<64,128,16,4,8,false,3>(stoch0, nullptr, W_is, xbuf, b_is, ae,
                                                 B_SZ, H_, S_, 0);
        } else {
            dim3 g(H_ / 256, B_SZ);
            x_gather_kernel<<<g, 256>>>(ae, b_is, W_is, idxb, xbuf);
        }
        launch_sgemm3<128,128,16,8,8,true,0>(xbuf, deter, W_gru, parts, nullptr, nullptr,
                                             B_SZ, 3 * D_, H_ + D_, H_);
        ln_gru_kernel<<<B_SZ, 256>>>(parts, ln_g, ln_b, deter,
                                     deters + (size_t)t * SL);
        launch_sgemm3<64,128,16,4,8,false,3>(deter, nullptr, W_od, hbuf, b_od, oe,
                                             B_SZ, H_, D_, 0);
        launch_sgemm3<64,64,16,4,4,false,1>(hbuf, nullptr, W_op,
                                            posts + (size_t)t * B_SZ * S_, b_op, nullptr,
                                            B_SZ, S_, H_, 0);
        sample_kernel<<<(B_SZ * K_ * 32) / 256, 256>>>(
            posts + (size_t)t * B_SZ * S_, unif + (size_t)t * B_SZ * K_ * V_,
            idxb, stochs + (size_t)t * B_SZ * S_);
    }

    // ======= priors: tensor-core bf16x6 (no feedback; output tolerance 1e-3) =======
    const size_t psTB_D = (size_t)TB * D_;
    const size_t psTB_H = (size_t)TB * H_;
    { dim3 g(D_ / 256, TB); split_kernel<<<g, 256>>>(deters, dsp, psTB_D, D_); }
    launch_mm<2, false, true>(dsp, psTB_D, Wio_s, nullptr, b_io, php, psTB_H,
                              TB, H_, D_);
    launch_mm<1, true, false>(php, psTB_H, Wip_s, priors, b_ip, nullptr, 0,
                              TB, S_, H_);
}

// round 17
// speedup vs baseline: 1.4383x; 1.2458x over previous
#include <cuda_runtime.h>
#include <cuda_bf16.h>
#include <math.h>
#include <stdint.h>

#define T_STEPS 64
#define B_SZ    512
#define OBS_    1536
#define ACT_    32
#define D_      2048
#define H_      2048
#define K_      32
#define V_      32
#define S_      1024
#define SL      (B_SZ * D_)
#define TB      (T_STEPS * B_SZ)
typedef __nv_bfloat16 bf16;

// ---------------- device scratch ----------------
__device__ float g_obs_e[(size_t)TB * H_];
__device__ float g_act_e[(size_t)TB * H_];
__device__ float g_x[(size_t)B_SZ * H_];
__device__ float g_parts[(size_t)B_SZ * 3 * D_];
__device__ float g_h[(size_t)B_SZ * H_];
__device__ float g_deter[(size_t)B_SZ * D_];
__device__ int   g_idx[B_SZ * K_];
// priors TC path
__device__ bf16 g_dsp[3 * (size_t)TB * D_];
__device__ bf16 g_php[3 * (size_t)TB * H_];
__device__ bf16 g_Wio_s[3 * (size_t)H_ * D_];
__device__ bf16 g_Wip_s[3 * (size_t)S_ * H_];

// ---------------- helpers ----------------
__device__ __forceinline__ uint32_t smem_u32(const void* p) {
    uint32_t a;
    asm("{ .reg .u64 t; cvta.to.shared.u64 t, %1; cvt.u32.u64 %0, t; }" : "=r"(a) : "l"(p));
    return a;
}
__device__ __forceinline__ void cp_async16(void* smem_dst, const void* gmem_src) {
    unsigned s = (unsigned)__cvta_generic_to_shared(smem_dst);
    asm volatile("cp.async.ca.shared.global [%0], [%1], 16;\n" :: "r"(s), "l"(gmem_src));
}
__device__ __forceinline__ void cp16(uint32_t dst, const void* src) {
    asm volatile("cp.async.cg.shared.global [%0], [%1], 16;\n" :: "r"(dst), "l"(src));
}
__device__ __forceinline__ void cp_commit() { asm volatile("cp.async.commit_group;\n" ::: "memory"); }
__device__ __forceinline__ void cp_wait1()  { asm volatile("cp.async.wait_group 1;\n" ::: "memory"); }
__device__ __forceinline__ void cp_wait0()  { asm volatile("cp.async.wait_group 0;\n" ::: "memory"); }
__device__ __forceinline__ void ffma2(unsigned long long& acc, unsigned long long a,
                                      unsigned long long b) {
    asm volatile("fma.rn.f32x2 %0, %1, %2, %0;\n" : "+l"(acc) : "l"(a), "l"(b));
}
__device__ __forceinline__ unsigned long long dup_f32(float b) {
    unsigned long long u;
    asm("mov.b64 %0, {%1, %1};\n" : "=l"(u) : "f"(b));
    return u;
}
__device__ __forceinline__ float2 ull2f2(unsigned long long v) {
    float2 r;
    r.x = __uint_as_float((unsigned)(v & 0xffffffffull));
    r.y = __uint_as_float((unsigned)(v >> 32));
    return r;
}
__device__ __forceinline__ uint4 ldmx4(uint32_t a) {
    uint4 v;
    asm volatile("ldmatrix.sync.aligned.m8n8.x4.shared.b16 {%0,%1,%2,%3}, [%4];"
                 : "=r"(v.x), "=r"(v.y), "=r"(v.z), "=r"(v.w) : "r"(a));
    return v;
}
__device__ __forceinline__ void mma_bf16(float* c, const uint4& a, uint32_t b0, uint32_t b1) {
    asm volatile("mma.sync.aligned.m16n8k16.row.col.f32.bf16.bf16.f32 "
        "{%0,%1,%2,%3}, {%4,%5,%6,%7}, {%8,%9}, {%0,%1,%2,%3};"
        : "+f"(c[0]), "+f"(c[1]), "+f"(c[2]), "+f"(c[3])
        : "r"(a.x), "r"(a.y), "r"(a.z), "r"(a.w), "r"(b0), "r"(b1));
}
__device__ __forceinline__ void bf16_split3(float x, bf16& h, bf16& m, bf16& l) {
    h = __float2bfloat16_rn(x);
    float r = x - __bfloat162float(h);
    m = __float2bfloat16_rn(r);
    r -= __bfloat162float(m);
    l = __float2bfloat16_rn(r);
}

// ================= SIMT fp32 SGEMM (bitwise-safe ascending-k chain) ================
// EPI: 0=none, 1=+bias, 2=+bias,ELU, 3=+bias,+addmat,ELU
template<int BM, int BN, int BK, int TM, int TN, bool CONCAT, int EPI, int MINB>
__global__ void __launch_bounds__(256, MINB)
sgemm3_kernel(const float* __restrict__ A, const float* __restrict__ A2,
              const float* __restrict__ B, float* __restrict__ C,
              const float* __restrict__ bias, const float* __restrict__ addm,
              int M, int N, int K, int K1)
{
    constexpr int THREADS = (BM/TM)*(BN/TN);
    static_assert(THREADS == 256, "expect 256 threads");
    constexpr int AROW = BM + 4;
    extern __shared__ __align__(16) float smemf[];
    float* As = smemf;
    float* Bs = smemf + 2*BK*AROW;

    const int tid = threadIdx.x;
    const int tx  = tid % (BN/TN);
    const int ty  = tid / (BN/TN);
    const int bm  = blockIdx.y * BM;
    const int bn  = blockIdx.x * BN;

    constexpr int A_TPR = BK / 4;
    constexpr int A_RS  = THREADS / A_TPR;
    constexpr int A_IT  = BM / A_RS;
    const int a_r = tid / A_TPR;
    const int a_c = (tid % A_TPR) * 4;

    constexpr int B_TPR = BN / 4;
    constexpr int B_RS  = THREADS / B_TPR;
    constexpr int B_IT  = BK / B_RS;
    const int b_r = tid / B_TPR;
    const int b_c = (tid % B_TPR) * 4;

    float4 ar[A_IT];
    unsigned long long acc[TM/2][TN];
    #pragma unroll
    for (int i = 0; i < TM/2; ++i)
        #pragma unroll
        for (int j = 0; j < TN; ++j) acc[i][j] = 0ull;

    auto a_gload = [&](int kt) {
        const int k0 = kt * BK;
        #pragma unroll
        for (int i = 0; i < A_IT; ++i) {
            int gr = bm + a_r + i * A_RS;
            int gk = k0 + a_c;
            const float* src;
            if (CONCAT) {
                src = (gk < K1) ? (A  + (size_t)gr * K1       + gk)
                                : (A2 + (size_t)gr * (K - K1) + (gk - K1));
            } else {
                src = A + (size_t)gr * K + gk;
            }
            ar[i] = *(const float4*)src;
        }
    };
    auto a_sstore = [&](int bf) {
        float* base = As + (size_t)bf * BK * AROW;
        #pragma unroll
        for (int i = 0; i < A_IT; ++i) {
            int r = a_r + i * A_RS;
            base[(a_c + 0) * AROW + r] = ar[i].x;
            base[(a_c + 1) * AROW + r] = ar[i].y;
            base[(a_c + 2) * AROW + r] = ar[i].z;
            base[(a_c + 3) * AROW + r] = ar[i].w;
        }
    };
    auto b_gload = [&](int kt, int bf) {
        const int k0 = kt * BK;
        float* base = Bs + (size_t)bf * BK * BN;
        #pragma unroll
        for (int i = 0; i < B_IT; ++i) {
            int r = b_r + i * B_RS;
            cp_async16(base + r * BN + b_c, B + (size_t)(k0 + r) * N + bn + b_c);
        }
        cp_commit();
    };

    const int ntiles = K / BK;
    b_gload(0, 0);
    a_gload(0);
    a_sstore(0);
    cp_wait0();
    __syncthreads();

    int buf = 0;
    for (int kt = 0; kt < ntiles; ++kt) {
        if (kt + 1 < ntiles) {
            b_gload(kt + 1, buf ^ 1);
            a_gload(kt + 1);
        }
        const float* Asb = As + (size_t)buf * BK * AROW;
        const float* Bsb = Bs + (size_t)buf * BK * BN;
        #pragma unroll
        for (int kk = 0; kk < BK; ++kk) {
            unsigned long long apair[TM/2];
            #pragma unroll
            for (int i4 = 0; i4 < TM/4; ++i4) {
                ulonglong2 p = *(const ulonglong2*)(Asb + kk * AROW + ty * TM + 4 * i4);
                apair[2*i4]     = p.x;
                apair[2*i4 + 1] = p.y;
            }
            unsigned long long bdup[TN];
            #pragma unroll
            for (int j4 = 0; j4 < TN/4; ++j4) {
                float4 bv = *(const float4*)(Bsb + kk * BN + tx * TN + 4 * j4);
                bdup[4*j4 + 0] = dup_f32(bv.x);
                bdup[4*j4 + 1] = dup_f32(bv.y);
                bdup[4*j4 + 2] = dup_f32(bv.z);
                bdup[4*j4 + 3] = dup_f32(bv.w);
            }
            #pragma unroll
            for (int i = 0; i < TM/2; ++i)
                #pragma unroll
                for (int j = 0; j < TN; ++j)
                    ffma2(acc[i][j], apair[i], bdup[j]);
        }
        if (kt + 1 < ntiles) {
            a_sstore(buf ^ 1);
            cp_wait0();
        }
        __syncthreads();
        buf ^= 1;
    }

    #pragma unroll
    for (int i2 = 0; i2 < TM/2; ++i2) {
        int row0 = bm + ty * TM + 2 * i2;
        float lo[TN], hi[TN];
        #pragma unroll
        for (int j = 0; j < TN; ++j) {
            float2 v = ull2f2(acc[i2][j]);
            lo[j] = v.x; hi[j] = v.y;
        }
        #pragma unroll
        for (int half = 0; half < 2; ++half) {
            int row = row0 + half;
            float* vals = half ? hi : lo;
            #pragma unroll
            for (int j = 0; j < TN; ++j) {
                int col = bn + tx * TN + j;
                float v = vals[j];
                if (EPI >= 1) v += bias[col];
                if (EPI == 3) v += addm[(size_t)row * N + col];
                if (EPI >= 2) v = (v > 0.f) ? v : expm1f(v);
                vals[j] = v;
            }
            #pragma unroll
            for (int j4 = 0; j4 < TN/4; ++j4)
                *(float4*)(C + (size_t)row * N + bn + tx * TN + 4 * j4) =
                    *(const float4*)(vals + 4 * j4);
        }
    }
}

template<int BM, int BN, int BK, int TM, int TN, bool CONCAT, int EPI, int MINB>
static void launch_sgemm3(const float* A, const float* A2, const float* B, float* C,
                          const float* bias, const float* addm,
                          int M, int N, int K, int K1)
{
    constexpr int AROW = BM + 4;
    constexpr size_t SMEM = (size_t)(2*BK*AROW + 2*BK*BN) * sizeof(float);
    cudaFuncSetAttribute((const void*)sgemm3_kernel<BM,BN,BK,TM,TN,CONCAT,EPI,MINB>,
                         cudaFuncAttributeMaxDynamicSharedMemorySize, (int)SMEM);
    dim3 g(N / BN, M / BM);
    sgemm3_kernel<BM,BN,BK,TM,TN,CONCAT,EPI,MINB><<<g, 256, SMEM>>>(
        A, A2, B, C, bias, addm, M, N, K, K1);
}

// ================= bf16x6 dual-acc TC GEMM (priors only) =================
#define MM_SMEM 196608

template<int EPI, bool WC, bool SO>
__global__ void __launch_bounds__(256)
mm_gemm(const bf16* __restrict__ A0, size_t aps0,
        const bf16* __restrict__ Bt,
        float* __restrict__ C, const float* __restrict__ bias,
        bf16* __restrict__ Co, size_t cps,
        int M, int N, int K)
{
    extern __shared__ __align__(16) char smem[];
    const uint32_t sb = smem_u32(smem);
    const int tid = threadIdx.x;
    const int w = tid >> 5, lane = tid & 31;
    const int gid = lane >> 2, tig = lane & 3;
    const int wm = w >> 1, wn = w & 1;
    const int bm = blockIdx.y * 128, bn = blockIdx.x * 128;
    const int NT = K / 64;
    const size_t bps = (size_t)N * K;

    float acc1[2][8][4], acc2[2][8][4];
    #pragma unroll
    for (int i = 0; i < 2; ++i)
        #pragma unroll
        for (int j = 0; j < 8; ++j)
            #pragma unroll
            for (int q = 0; q < 4; ++q) { acc1[i][j][q] = 0.f; acc2[i][j][q] = 0.f; }

    auto load_tile = [&](int kt, int s) {
        uint32_t ab = sb + s * 98304u;
        #pragma unroll
        for (int i = 0; i < 12; ++i) {
            int id = tid + 256 * i;
            int p = id >> 10, rem = id & 1023;
            int row = rem >> 3, ch = rem & 7;
            uint32_t off = (uint32_t)(p * 16384 + row * 128 + ((ch ^ (row & 7)) * 16));
            cp16(ab + off, A0 + p * aps0 + (size_t)(bm + row) * K + kt * 64 + ch * 8);
            cp16(ab + 49152u + off, Bt + p * bps + (size_t)(bn + row) * K + kt * 64 + ch * 8);
        }
        cp_commit();
    };

    const int a_roff = lane & 15;
    const int a_csel = lane >> 4;
    const int b_roff = (lane & 7) + ((lane >> 4) << 3);
    const int b_csel = (lane >> 3) & 1;

    load_tile(0, 0);
    for (int kt = 0; kt < NT; ++kt) {
        int s = kt & 1;
        if (kt + 1 < NT) load_tile(kt + 1, s ^ 1);
        if (kt + 1 < NT) cp_wait1(); else cp_wait0();
        __syncthreads();
        uint32_t ab = sb + s * 98304u, bb = ab + 49152u;
        #pragma unroll
        for (int g = 0; g < 4; ++g) {
            uint4 aF[3][2];
            #pragma unroll
            for (int p = 0; p < 3; ++p)
                #pragma unroll
                for (int mi = 0; mi < 2; ++mi) {
                    int r = wm * 32 + mi * 16 + a_roff;
                    int ch = 2 * g + a_csel;
                    aF[p][mi] = ldmx4(ab + p * 16384u +
                        (uint32_t)(r * 128 + ((ch ^ (r & 7)) * 16)));
                }
            #pragma unroll
            for (int no = 0; no < 4; ++no) {
                int r = wn * 64 + no * 16 + b_roff;
                int ch = 2 * g + b_csel;
                uint32_t boff = (uint32_t)(r * 128 + ((ch ^ (r & 7)) * 16));
                uint4 bH = ldmx4(bb + boff);
                uint4 bM = ldmx4(bb + 16384u + boff);
                uint4 bL = ldmx4(bb + 32768u + boff);
                #pragma unroll
                for (int half = 0; half < 2; ++half) {
                    int ni = 2 * no + half;
                    uint32_t h0 = half ? bH.z : bH.x, h1 = half ? bH.w : bH.y;
                    uint32_t m0 = half ? bM.z : bM.x, m1 = half ? bM.w : bM.y;
                    uint32_t l0 = half ? bL.z : bL.x, l1 = half ? bL.w : bL.y;
                    #pragma unroll
                    for (int mi = 0; mi < 2; ++mi) {
                        mma_bf16(acc1[mi][ni], aF[0][mi], h0, h1);
                        mma_bf16(acc2[mi][ni], aF[0][mi], m0, m1);
                        mma_bf16(acc2[mi][ni], aF[1][mi], h0, h1);
                        mma_bf16(acc2[mi][ni], aF[0][mi], l0, l1);
                        mma_bf16(acc2[mi][ni], aF[2][mi], h0, h1);
                        mma_bf16(acc2[mi][ni], aF[1][mi], m0, m1);
                    }
                }
            }
        }
        __syncthreads();
    }

    #pragma unroll
    for (int mi = 0; mi < 2; ++mi)
        #pragma unroll
        for (int ni = 0; ni < 8; ++ni) {
            int col = bn + wn * 64 + ni * 8 + 2 * tig;
            #pragma unroll
            for (int hf = 0; hf < 2; ++hf) {
                int row = bm + wm * 32 + mi * 16 + gid + hf * 8;
                float v0 = acc1[mi][ni][2 * hf]     + acc2[mi][ni][2 * hf];
                float v1 = acc1[mi][ni][2 * hf + 1] + acc2[mi][ni][2 * hf + 1];
                if (EPI >= 1) { v0 += bias[col]; v1 += bias[col + 1]; }
                if (EPI >= 2) {
                    v0 = (v0 > 0.f) ? v0 : expm1f(v0);
                    v1 = (v1 > 0.f) ? v1 : expm1f(v1);
                }
                if (WC)
                    *(float2*)(C + (size_t)row * N + col) = make_float2(v0, v1);
                if (SO) {
                    bf16 h, m, l;
                    size_t p0 = (size_t)row * N + col;
                    bf16_split3(v0, h, m, l);
                    Co[p0] = h; Co[cps + p0] = m; Co[2 * cps + p0] = l;
                    bf16_split3(v1, h, m, l);
                    Co[p0 + 1] = h; Co[cps + p0 + 1] = m; Co[2 * cps + p0 + 1] = l;
                }
            }
        }
}

template<int EPI, bool WC, bool SO>
static void launch_mm(const bf16* A0, size_t aps0, const bf16* Bt, float* C,
                      const float* bias, bf16* Co, size_t cps, int M, int N, int K)
{
    cudaFuncSetAttribute((const void*)mm_gemm<EPI, WC, SO>,
                         cudaFuncAttributeMaxDynamicSharedMemorySize, MM_SMEM);
    dim3 g(N / 128, M / 128);
    mm_gemm<EPI, WC, SO><<<g, 256, MM_SMEM>>>(A0, aps0, Bt, C, bias, Co, cps, M, N, K);
}

// ---------------- bf16 preprocessing (priors path only) ----------------
__global__ void tsplit_kernel(const float* __restrict__ W, bf16* __restrict__ T,
                              int Kd, int Nd)
{
    __shared__ float t[32][33];
    int n0 = blockIdx.x * 32, k0 = blockIdx.y * 32;
    for (int i = threadIdx.y; i < 32; i += 8)
        t[i][threadIdx.x] = W[(size_t)(k0 + i) * Nd + n0 + threadIdx.x];
    __syncthreads();
    size_t ps = (size_t)Nd * Kd;
    for (int i = threadIdx.y; i < 32; i += 8) {
        bf16 h, m, l;
        bf16_split3(t[threadIdx.x][i], h, m, l);
        size_t pos = (size_t)(n0 + i) * Kd + k0 + threadIdx.x;
        T[pos] = h; T[ps + pos] = m; T[2 * ps + pos] = l;
    }
}
__global__ void split_kernel(const float* __restrict__ X, bf16* __restrict__ O,
                             size_t ps, int F)
{
    int j = blockIdx.x * 256 + threadIdx.x;
    if (j >= F) return;
    size_t row = blockIdx.y;
    bf16 h, m, l;
    bf16_split3(X[row * F + j], h, m, l);
    size_t pos = row * F + j;
    O[pos] = h; O[ps + pos] = m; O[2 * ps + pos] = l;
}

// ---------------- x = elu(ae + b_is + one-hot gather of W_is) ----------------
__global__ void x_gather_kernel(const float* __restrict__ ae, const float* __restrict__ b_is,
                                const float* __restrict__ W_is, const int* __restrict__ idx,
                                float* __restrict__ x)
{
    int j = blockIdx.x * blockDim.x + threadIdx.x;
    int b = blockIdx.y;
    __shared__ int sid[K_];
    if (threadIdx.x < K_) sid[threadIdx.x] = idx[b * K_ + threadIdx.x];
    __syncthreads();
    float v = ae[(size_t)b * H_ + j] + b_is[j];
    #pragma unroll
    for (int k = 0; k < K_; ++k)
        v += W_is[(size_t)sid[k] * H_ + j];
    x[(size_t)b * H_ + j] = (v > 0.f) ? v : expm1f(v);
}

// ---------------- fused LayerNorm + GRU gates (R4-verbatim numerics) ----------------
__global__ void ln_gru_kernel(const float* __restrict__ parts,
                              const float* __restrict__ ln_g,
                              const float* __restrict__ ln_b,
                              float* __restrict__ deter,
                              float* __restrict__ deters_out)
{
    const int row = blockIdx.x;
    const float* p = parts + (size_t)row * (3 * D_);
    float s = 0.f, s2 = 0.f;
    for (int i = threadIdx.x * 4; i < 3 * D_; i += 256 * 4) {
        float4 v = *(const float4*)(p + i);
        s  += v.x + v.y + v.z + v.w;
        s2 += v.x * v.x + v.y * v.y + v.z * v.z + v.w * v.w;
    }
    __shared__ float shs[8], shs2[8];
    #pragma unroll
    for (int off = 16; off > 0; off >>= 1) {
        s  += __shfl_down_sync(0xffffffffu, s,  off);
        s2 += __shfl_down_sync(0xffffffffu, s2, off);
    }
    int warp = threadIdx.x >> 5, lane = threadIdx.x & 31;
    if (lane == 0) { shs[warp] = s; shs2[warp] = s2; }
    __syncthreads();
    __shared__ float sh_m, sh_rstd;
    if (threadIdx.x == 0) {
        float S = 0.f, S2 = 0.f;
        #pragma unroll
        for (int i = 0; i < 8; ++i) { S += shs[i]; S2 += shs2[i]; }
        float m   = S * (1.f / (3 * D_));
        float var = S2 * (1.f / (3 * D_)) - m * m;
        sh_m = m; sh_rstd = rsqrtf(var + 1e-5f);
    }
    __syncthreads();
    const float m = sh_m, rstd = sh_rstd;
    for (int j = threadIdx.x; j < D_; j += 256) {
        float r = (p[j]          - m) * rstd * ln_g[j]          + ln_b[j];
        float c = (p[j + D_]     - m) * rstd * ln_g[j + D_]     + ln_b[j + D_];
        float u = (p[j + 2 * D_] - m) * rstd * ln_g[j + 2 * D_] + ln_b[j + 2 * D_];
        float sr   = 1.f / (1.f + expf(-r));
        float cand = tanhf(sr * c);
        float up   = 1.f / (1.f + expf(-(u - 1.f)));
        float dprev = deter[(size_t)row * D_ + j];
        float dn = up * cand + (1.f - up) * dprev;
        deter[(size_t)row * D_ + j] = dn;
        deters_out[(size_t)row * D_ + j] = dn;
    }
}

// ---------------- gumbel-max sampling ----------------
__global__ void sample_kernel(const float* __restrict__ logits,
                              const float* __restrict__ unif,
                              int* __restrict__ idx_out,
                              float* __restrict__ stochs_out)
{
    int gw   = (blockIdx.x * blockDim.x + threadIdx.x) >> 5;
    int lane = threadIdx.x & 31;
    size_t base = (size_t)gw * V_ + lane;
    float logit = logits[base];
    float u = unif[base];
    u = fminf(fmaxf(u, 1e-5f), 1.0f - 1e-5f);
    float val = logit - logf(-logf(u));
    int idx = lane;
    #pragma unroll
    for (int off = 16; off > 0; off >>= 1) {
        float ov = __shfl_down_sync(0xffffffffu, val, off);
        int   oi = __shfl_down_sync(0xffffffffu, idx, off);
        if (ov > val || (ov == val && oi < idx)) { val = ov; idx = oi; }
    }
    idx = __shfl_sync(0xffffffffu, idx, 0);
    stochs_out[base] = (lane == idx) ? 1.0f : 0.0f;
    if (lane == 0) idx_out[gw] = ((gw & (K_ - 1)) << 5) | idx;
}

#define GSA(p, s) cudaGetSymbolAddress((void**)&p, s)

extern "C" void kernel_launch(void* const* d_in, const int* in_sizes, int n_in,
                              void* d_out, int out_size)
{
    (void)in_sizes; (void)n_in; (void)out_size;
    const float* obs    = (const float*)d_in[0];
    const float* act    = (const float*)d_in[1];
    const float* deter0 = (const float*)d_in[2];
    const float* stoch0 = (const float*)d_in[3];
    const float* unif   = (const float*)d_in[4];
    const float* W_oo = (const float*)d_in[5];  const float* b_oo = (const float*)d_in[6];
    const float* W_ia = (const float*)d_in[7];  const float* b_ia = (const float*)d_in[8];
    const float* W_is = (const float*)d_in[9];  const float* b_is = (const float*)d_in[10];
    const float* W_gru = (const float*)d_in[11];
    const float* ln_g = (const float*)d_in[12]; const float* ln_b = (const float*)d_in[13];
    const float* W_od = (const float*)d_in[14]; const float* b_od = (const float*)d_in[15];
    const float* W_op = (const float*)d_in[16]; const float* b_op = (const float*)d_in[17];
    const float* W_io = (const float*)d_in[18]; const float* b_io = (const float*)d_in[19];
    const float* W_ip = (const float*)d_in[20]; const float* b_ip = (const float*)d_in[21];

    float* out = (float*)d_out;
    float* deters = out;
    float* stochs = deters + (size_t)TB * D_;
    float* posts  = stochs + (size_t)TB * S_;
    float* priors = posts  + (size_t)TB * S_;

    float *obs_e, *act_e, *xbuf, *parts, *hbuf, *deter; int* idxb;
    bf16 *dsp, *php, *Wio_s, *Wip_s;
    GSA(obs_e, g_obs_e); GSA(act_e, g_act_e); GSA(xbuf, g_x);
    GSA(parts, g_parts); GSA(hbuf, g_h); GSA(deter, g_deter); GSA(idxb, g_idx);
    GSA(dsp, g_dsp); GSA(php, g_php); GSA(Wio_s, g_Wio_s); GSA(Wip_s, g_Wip_s);

    cudaMemcpyAsync(deter, deter0, (size_t)SL * sizeof(float), cudaMemcpyDeviceToDevice, 0);

    // priors weight splits (off the decision path)
    { dim3 g(H_ / 32, D_ / 32); tsplit_kernel<<<g, dim3(32, 8)>>>(W_io, Wio_s, D_, H_); }
    { dim3 g(S_ / 32, H_ / 32); tsplit_kernel<<<g, dim3(32, 8)>>>(W_ip, Wip_s, H_, S_); }

    // ======= decision path: R4-bitwise numerics, phase-model-tuned tiles =======
    launch_sgemm3<128,128,16,8,8,false,1,2>(obs, nullptr, W_oo, obs_e, b_oo, nullptr,
                                            TB, H_, OBS_, 0);
    launch_sgemm3<128,128,16,8,8,false,1,2>(act, nullptr, W_ia, act_e, b_ia, nullptr,
                                            TB, H_, ACT_, 0);

    for (int t = 0; t < T_STEPS; ++t) {
        const float* ae = act_e + (size_t)t * B_SZ * H_;
        const float* oe = obs_e + (size_t)t * B_SZ * H_;
        if (t == 0) {
            launch_sgemm3<64,128,16,4,8,false,3,3>(stoch0, nullptr, W_is, xbuf, b_is, ae,
                                                   B_SZ, H_, S_, 0);
        } else {
            dim3 g(H_ / 256, B_SZ);
            x_gather_kernel<<<g, 256>>>(ae, b_is, W_is, idxb, xbuf);
        }
        // GRU: 128x64 tile @3 CTAs/SM -> 384 CTAs (86% wave util), FFMA2-bound
        launch_sgemm3<128,64,16,8,4,true,0,3>(xbuf, deter, W_gru, parts, nullptr, nullptr,
                                              B_SZ, 3 * D_, H_ + D_, H_);
        ln_gru_kernel<<<B_SZ, 256>>>(parts, ln_g, ln_b, deter,
                                     deters + (size_t)t * SL);
        // W_od: 64x64 @4 CTAs/SM -> 256 CTAs
        launch_sgemm3<64,64,16,4,4,false,3,4>(deter, nullptr, W_od, hbuf, b_od, oe,
                                              B_SZ, H_, D_, 0);
        launch_sgemm3<64,64,16,4,4,false,1,4>(hbuf, nullptr, W_op,
                                              posts + (size_t)t * B_SZ * S_, b_op, nullptr,
                                              B_SZ, S_, H_, 0);
        sample_kernel<<<(B_SZ * K_ * 32) / 256, 256>>>(
            posts + (size_t)t * B_SZ * S_, unif + (size_t)t * B_SZ * K_ * V_,
            idxb, stochs + (size_t)t * B_SZ * S_);
    }

    // ======= priors: tensor-core bf16x6 (no feedback) =======
    const size_t psTB_D = (size_t)TB * D_;
    const size_t psTB_H = (size_t)TB * H_;
    { dim3 g(D_ / 256, TB); split_kernel<<<g, 256>>>(deters, dsp, psTB_D, D_); }
    launch_mm<2, false, true>(dsp, psTB_D, Wio_s, nullptr, b_io, php, psTB_H,
                              TB, H_, D_);
    launch_mm<1, true, false>(php, psTB_H, Wip_s, priors, b_ip, nullptr, 0,
                              TB, S_, H_);
}